// round 8
// baseline (speedup 1.0000x reference)
#include <cuda_runtime.h>
#include <cstdint>

#define DIM   512
#define NTOK  16384
#define BATCH 8
#define BPB   37                            // blocks per batch; 8*37 = 296 = 148 SMs * occ2
#define TOTAL_BLOCKS (BATCH * BPB)
#define D4    (DIM / 4)                     // 128 16-byte granules per token

#define STAGES        5
#define TOK_PER_STAGE 8
#define STAGE_BYTES   (TOK_PER_STAGE * DIM * 4)     // 16384
#define RING_BYTES    (STAGES * STAGE_BYTES)        // 81920
#define THREADS       288                           // warp 0 producer, warps 1..8 consumers

// Allocation-free scratch; fully rewritten every launch (graph-replay safe).
__device__ ulonglong2   g_partial_acc[TOTAL_BLOCKS * D4];   // packed f32x2 pairs
__device__ float        g_partial_l[TOTAL_BLOCKS];
__device__ unsigned int g_count[BATCH];   // zero-init; last block resets itself

// 2048 chunks over 37 blocks: first 13 blocks get 56 chunks, rest get 55.
__device__ __forceinline__ int chunk_start(int idx) {
    return idx * 55 + (idx < 13 ? idx : 13);
}

// ---- packed f32x2 helpers (sm_103a) ----
__device__ __forceinline__ unsigned long long fma2(unsigned long long a,
                                                   unsigned long long b,
                                                   unsigned long long c) {
    unsigned long long d;
    asm("fma.rn.f32x2 %0, %1, %2, %3;" : "=l"(d) : "l"(a), "l"(b), "l"(c));
    return d;
}
__device__ __forceinline__ unsigned long long add2(unsigned long long a,
                                                   unsigned long long b) {
    unsigned long long d;
    asm("add.rn.f32x2 %0, %1, %2;" : "=l"(d) : "l"(a), "l"(b));
    return d;
}
__device__ __forceinline__ unsigned long long mul2(unsigned long long a,
                                                   unsigned long long b) {
    unsigned long long d;
    asm("mul.rn.f32x2 %0, %1, %2;" : "=l"(d) : "l"(a), "l"(b));
    return d;
}
__device__ __forceinline__ unsigned long long pack2(float lo, float hi) {
    unsigned long long d;
    asm("mov.b64 %0, {%1, %2};" : "=l"(d) : "f"(lo), "f"(hi));
    return d;
}
__device__ __forceinline__ float hsum2(unsigned long long v) {
    float lo, hi;
    asm("mov.b64 {%0, %1}, %2;" : "=f"(lo), "=f"(hi) : "l"(v));
    return lo + hi;
}
__device__ __forceinline__ float tanh_fast(float x) {
    float r;
    asm("tanh.approx.f32 %0, %1;" : "=f"(r) : "f"(x));
    return r;
}
__device__ __forceinline__ float exp2_fast(float x) {
    float r;
    asm("ex2.approx.f32 %0, %1;" : "=f"(r) : "f"(x));
    return r;
}

// ---- mbarrier helpers ----
__device__ __forceinline__ uint32_t smem_u32(const void* p) {
    uint32_t a;
    asm("{ .reg .u64 t; cvta.to.shared.u64 t, %1; cvt.u32.u64 %0, t; }" : "=r"(a) : "l"(p));
    return a;
}
#define MBAR_INIT(addr, cnt) \
    asm volatile("mbarrier.init.shared.b64 [%0], %1;" :: "r"(addr), "r"(cnt) : "memory")
#define MBAR_EXPECT_TX(addr, bytes) \
    asm volatile("mbarrier.arrive.expect_tx.shared.b64 _, [%0], %1;" :: "r"(addr), "r"(bytes) : "memory")
#define MBAR_ARRIVE(addr) \
    asm volatile("mbarrier.arrive.shared.b64 _, [%0];" :: "r"(addr) : "memory")
#define MBAR_WAIT_ACQ(addr, ph) do {                                              \
    asm volatile("{\n\t.reg .pred P;\n\t"                                          \
        "WL_%=:\n\t"                                                               \
        "mbarrier.try_wait.parity.acquire.cta.shared::cta.b64 P, [%0], %1, 0x989680;\n\t" \
        "@P bra WD_%=;\n\t"                                                        \
        "bra WL_%=;\n\t"                                                           \
        "WD_%=:\n\t}" :: "r"(addr), "r"(ph) : "memory");                           \
} while (0)
#define MBAR_WAIT_RLX(addr, ph) do {                                              \
    asm volatile("{\n\t.reg .pred P;\n\t"                                          \
        "WL_%=:\n\t"                                                               \
        "mbarrier.try_wait.parity.relaxed.cta.shared::cta.b64 P, [%0], %1, 0x989680;\n\t" \
        "@P bra WD_%=;\n\t"                                                        \
        "bra WL_%=;\n\t"                                                           \
        "WD_%=:\n\t}" :: "r"(addr), "r"(ph) : "memory");                           \
} while (0)
#define BULK_G2S(dst, src, bytes, mbar)                                            \
    asm volatile("cp.async.bulk.shared::cluster.global.mbarrier::complete_tx::bytes " \
                 "[%0], [%1], %2, [%3];"                                           \
                 :: "r"(dst), "l"(src), "r"(bytes), "r"(mbar) : "memory")

__global__ __launch_bounds__(THREADS, 2)
void ga_fused(const float* __restrict__ x,
              const float* __restrict__ Wa, const float* __restrict__ ba,
              const float* __restrict__ Wg, const float* __restrict__ bg,
              float* __restrict__ out)
{
    extern __shared__ char ring[];                    // 80 KB
    __shared__ __align__(8) unsigned long long mbar[2 * STAGES]; // [2s]=full, [2s+1]=empty
    __shared__ float s_l[8];
    __shared__ unsigned int s_last;

    const int blk = blockIdx.x;
    const int b   = blk / BPB;
    const int idx = blk % BPB;
    const int tid = threadIdx.x;
    const int w   = tid >> 5;
    const int L   = tid & 31;

    const uint32_t ring32 = smem_u32(ring);
    const uint32_t mb32   = smem_u32(mbar);

    // Weights as packed f32x2 pairs; issued before init barrier to overlap latency.
    const ulonglong2* Wa2 = reinterpret_cast<const ulonglong2*>(Wa);
    const ulonglong2* Wg2 = reinterpret_cast<const ulonglong2*>(Wg);
    ulonglong2 wa[4], wg[4];
#pragma unroll
    for (int j = 0; j < 4; ++j) { wa[j] = Wa2[j * 32 + L]; wg[j] = Wg2[j * 32 + L]; }
    const float b_a = *ba;
    const float b_g = *bg;

    if (tid == 0) {
#pragma unroll
        for (int s = 0; s < STAGES; ++s) {
            MBAR_INIT(mb32 + 16u * s,     1u);   // full: completed by TX bytes
            MBAR_INIT(mb32 + 16u * s + 8, 8u);   // empty: 8 consumer-warp arrivals
        }
    }
    __syncthreads();

    const int c0  = chunk_start(idx);
    const int nch = chunk_start(idx + 1) - c0;
    const float* xb = x + (size_t)b * NTOK * DIM;

    unsigned long long acc[8];
#pragma unroll
    for (int k = 0; k < 8; ++k) acc[k] = 0ull;   // 0ull == packed {0.f, 0.f}
    float l = 0.f;

    if (w == 0) {
        // ---------------- producer warp (R4-exact) ----------------
        int stage = 0, phase = 1;                  // fresh barrier: parity-1 wait passes
        for (int c = 0; c < nch; ++c) {
            MBAR_WAIT_RLX(mb32 + 16u * stage + 8, phase);
            if (L == 0) {
                MBAR_EXPECT_TX(mb32 + 16u * stage, (unsigned)STAGE_BYTES);
                const float* src = xb + (size_t)(c0 + c) * TOK_PER_STAGE * DIM;
                BULK_G2S(ring32 + stage * STAGE_BYTES, src, (unsigned)STAGE_BYTES,
                         mb32 + 16u * stage);
            }
            if (++stage == STAGES) { stage = 0; phase ^= 1; }
        }
    } else {
        // ------------- consumer warps cw=0..7: one token per stage -------------
        const int cw = w - 1;
        int stage = 0, phase = 0;
        for (int c = 0; c < nch; ++c) {
            MBAR_WAIT_ACQ(mb32 + 16u * stage, phase);
            const ulonglong2* tok = reinterpret_cast<const ulonglong2*>(
                ring + stage * STAGE_BYTES + cw * (DIM * 4));
            ulonglong2 xv[4];
#pragma unroll
            for (int j = 0; j < 4; ++j) xv[j] = tok[j * 32 + L];

            // Packed dual dots: 16 fma.f32x2 total (vs 32 scalar FMA).
            unsigned long long dap = 0ull, dgp = 0ull;
#pragma unroll
            for (int j = 0; j < 4; ++j) {
                dap = fma2(xv[j].x, wa[j].x, dap);
                dap = fma2(xv[j].y, wa[j].y, dap);
                dgp = fma2(xv[j].x, wg[j].x, dgp);
                dgp = fma2(xv[j].y, wg[j].y, dgp);
            }
            float da = hsum2(dap);
            float dg = hsum2(dgp);
#pragma unroll
            for (int off = 16; off > 0; off >>= 1) {
                da += __shfl_xor_sync(0xffffffffu, da, off);
                dg += __shfl_xor_sync(0xffffffffu, dg, off);
            }
            // Fast activations: MUFU.TANH for both; exp via ex2.
            const float attn = tanh_fast(da + b_a);
            const float gate = fmaf(0.5f, tanh_fast(fmaf(0.5f, dg, 0.5f * b_g)), 0.5f);
            const float p    = exp2_fast(attn * gate * 1.442695041f);

            l += p;
            const unsigned long long pp = pack2(p, p);
#pragma unroll
            for (int j = 0; j < 4; ++j) {
                acc[2 * j]     = fma2(pp, xv[j].x, acc[2 * j]);
                acc[2 * j + 1] = fma2(pp, xv[j].y, acc[2 * j + 1]);
            }
            // xv fully consumed -> release the stage.
            if (L == 0) MBAR_ARRIVE(mb32 + 16u * stage + 8);
            if (++stage == STAGES) { stage = 0; phase ^= 1; }
        }
    }
    __syncthreads();   // ring is dead -> reuse as combine buffer

    ulonglong2* s_acc = reinterpret_cast<ulonglong2*>(ring);   // 8 warps * 128 * 16B = 16 KB
    if (w >= 1) {
#pragma unroll
        for (int j = 0; j < 4; ++j)
            s_acc[(w - 1) * D4 + j * 32 + L] = make_ulonglong2(acc[2 * j], acc[2 * j + 1]);
        if (L == 0) s_l[w - 1] = l;
    }
    __syncthreads();

    if (tid < D4) {
        unsigned long long sx = 0ull, sy = 0ull;
#pragma unroll
        for (int ww = 0; ww < 8; ++ww) {
            ulonglong2 v = s_acc[ww * D4 + tid];
            sx = add2(sx, v.x);
            sy = add2(sy, v.y);
        }
        g_partial_acc[blk * D4 + tid] = make_ulonglong2(sx, sy);
    }
    if (tid == 0) {
        float lt = 0.f;
#pragma unroll
        for (int ww = 0; ww < 8; ++ww) lt += s_l[ww];
        g_partial_l[blk] = lt;
    }

    // ---- last block of this batch finishes the reduction ----
    __threadfence();
    if (tid == 0) {
        unsigned int old = atomicAdd(&g_count[b], 1u);
        s_last = (old == BPB - 1) ? 1u : 0u;
    }
    __syncthreads();
    if (s_last) {
        if (tid == 0) g_count[b] = 0;   // reset for next graph replay
        if (tid < D4) {
            unsigned long long sx = 0ull, sy = 0ull;
            float lsum = 0.f;
#pragma unroll
            for (int i = 0; i < BPB; ++i) {
                const int pb = b * BPB + i;
                ulonglong2 v = g_partial_acc[pb * D4 + tid];   // L2-hot
                sx = add2(sx, v.x);
                sy = add2(sy, v.y);
                lsum += g_partial_l[pb];
            }
            const float inv = __frcp_rn(lsum);
            const unsigned long long inv2 = pack2(inv, inv);
            reinterpret_cast<ulonglong2*>(out)[b * D4 + tid] =
                make_ulonglong2(mul2(sx, inv2), mul2(sy, inv2));
        }
    }
}

extern "C" void kernel_launch(void* const* d_in, const int* in_sizes, int n_in,
                              void* d_out, int out_size)
{
    const float* x  = (const float*)d_in[0];
    const float* Wa = (const float*)d_in[1];
    const float* ba = (const float*)d_in[2];
    const float* Wg = (const float*)d_in[3];
    const float* bg = (const float*)d_in[4];
    float* out = (float*)d_out;

    cudaFuncSetAttribute(ga_fused, cudaFuncAttributeMaxDynamicSharedMemorySize, RING_BYTES);
    ga_fused<<<TOTAL_BLOCKS, THREADS, RING_BYTES>>>(x, Wa, ba, Wg, bg, out);
}